// round 2
// baseline (speedup 1.0000x reference)
#include <cuda_runtime.h>
#include <cstdint>

// ---------------------------------------------------------------------------
// GCN decoder: 4 x (GCNConv [+ReLU] [+upsample x2 folded into next layer])
// Layer l: deg-count -> rsqrt -> GEMM(hs = dinv * x@W, acc=hs) ->
//          scatter(acc[dst] += hs[src], vector red.v4.f32) ->
//          finalize(out = dinv*acc + b [, relu])
// Upsample(repeat rows x2) is folded into the next GEMM via (row >> 1).
// Edge indices are int32 (JAX default x64-disabled downcasts int64 -> int32).
// ---------------------------------------------------------------------------

#define MAXN 200000
#define MAXF 6400000

__device__ __align__(256) float g_deg[MAXN];
__device__ __align__(256) float g_hs [MAXF];
__device__ __align__(256) float g_acc[MAXF];
__device__ __align__(256) float g_p1 [MAXF];   // ping
__device__ __align__(256) float g_p2 [MAXF];   // pong

// ---------------- small helper kernels ----------------

__global__ void k_init_deg(float* deg, int M) {
    int i = blockIdx.x * blockDim.x + threadIdx.x;
    if (i < M) deg[i] = 1.0f;                 // self loop
}

__global__ void k_count_deg(const int* __restrict__ dst,
                            float* __restrict__ deg, int E) {
    int i = blockIdx.x * blockDim.x + threadIdx.x;
    if (i < E) atomicAdd(&deg[dst[i]], 1.0f);
}

__global__ void k_rsqrt(float* deg, int M) {
    int i = blockIdx.x * blockDim.x + threadIdx.x;
    if (i < M) deg[i] = rsqrtf(deg[i]);
}

// ---------------- tiled GEMM: hs = dinv[row] * (X[row>>shift] @ W) ----------
// BM=64, BN=64, BK=16, 256 threads, 4x4 microtile per thread.
// Requires K % 16 == 0 and F % 64 == 0 (true for F in {256,128,64}).

__global__ void k_gemm_tiled(const float* __restrict__ X,
                             const float* __restrict__ W,
                             float* __restrict__ hs,
                             float* __restrict__ acc,
                             const float* __restrict__ dinv,
                             int M, int K, int F, int shift) {
    __shared__ float As[16][64];   // A transposed: As[k][row]
    __shared__ float Bs[16][64];

    const int tid = threadIdx.x;
    const int tx  = tid & 15;       // 0..15 -> 4 cols each
    const int ty  = tid >> 4;       // 0..15 -> 4 rows each
    const int row0 = blockIdx.y * 64;
    const int col0 = blockIdx.x * 64;

    // A loader: one float4 per thread
    const int arow = tid >> 2;            // 0..63
    const int ak   = (tid & 3) * 4;       // 0,4,8,12
    // B loader: one float4 per thread
    const int brow = tid >> 4;            // 0..15
    const int bc   = (tid & 15) * 4;      // 0..60

    float c[4][4] = {};

    for (int k0 = 0; k0 < K; k0 += 16) {
        int grow = row0 + arow;
        float4 av = make_float4(0.f, 0.f, 0.f, 0.f);
        if (grow < M) {
            av = *reinterpret_cast<const float4*>(
                X + (size_t)(grow >> shift) * K + k0 + ak);
        }
        As[ak + 0][arow] = av.x;
        As[ak + 1][arow] = av.y;
        As[ak + 2][arow] = av.z;
        As[ak + 3][arow] = av.w;

        float4 bv = *reinterpret_cast<const float4*>(
            W + (size_t)(k0 + brow) * F + col0 + bc);
        *reinterpret_cast<float4*>(&Bs[brow][bc]) = bv;

        __syncthreads();

        #pragma unroll
        for (int kk = 0; kk < 16; kk++) {
            float4 a = *reinterpret_cast<const float4*>(&As[kk][ty * 4]);
            float4 b = *reinterpret_cast<const float4*>(&Bs[kk][tx * 4]);
            c[0][0] += a.x * b.x; c[0][1] += a.x * b.y; c[0][2] += a.x * b.z; c[0][3] += a.x * b.w;
            c[1][0] += a.y * b.x; c[1][1] += a.y * b.y; c[1][2] += a.y * b.z; c[1][3] += a.y * b.w;
            c[2][0] += a.z * b.x; c[2][1] += a.z * b.y; c[2][2] += a.z * b.z; c[2][3] += a.z * b.w;
            c[3][0] += a.w * b.x; c[3][1] += a.w * b.y; c[3][2] += a.w * b.z; c[3][3] += a.w * b.w;
        }
        __syncthreads();
    }

    #pragma unroll
    for (int i = 0; i < 4; i++) {
        int row = row0 + ty * 4 + i;
        if (row < M) {
            float dv = dinv[row];
            float4 v = make_float4(c[i][0] * dv, c[i][1] * dv,
                                   c[i][2] * dv, c[i][3] * dv);
            size_t off = (size_t)row * F + col0 + tx * 4;
            *reinterpret_cast<float4*>(hs  + off) = v;
            *reinterpret_cast<float4*>(acc + off) = v;
        }
    }
}

// ---------------- small-F GEMM (layer 4: K=64, F=8) -------------------------
// 256 threads = (256/F) nodes x F cols per block, W in smem.

__global__ void k_gemm_small(const float* __restrict__ X,
                             const float* __restrict__ W,
                             float* __restrict__ hs,
                             float* __restrict__ acc,
                             const float* __restrict__ dinv,
                             int M, int K, int F, int shift) {
    __shared__ float Ws[512];                 // K*F <= 512
    for (int i = threadIdx.x; i < K * F; i += blockDim.x) Ws[i] = W[i];
    __syncthreads();

    int npb = blockDim.x / F;
    int n = blockIdx.x * npb + threadIdx.x / F;
    int f = threadIdx.x % F;
    if (n >= M) return;

    const float* xr = X + (size_t)(n >> shift) * K;
    float s = 0.f;
    #pragma unroll 8
    for (int k = 0; k < K; k++) s += xr[k] * Ws[k * F + f];

    float v = s * dinv[n];
    hs [(size_t)n * F + f] = v;
    acc[(size_t)n * F + f] = v;
}

// ---------------- edge scatter: acc[dst] += hs[src] (float4 reductions) -----

__device__ __forceinline__ void red_add_v4(float4* addr, float4 v) {
    asm volatile("red.global.add.v4.f32 [%0], {%1, %2, %3, %4};"
                 :: "l"(addr), "f"(v.x), "f"(v.y), "f"(v.z), "f"(v.w)
                 : "memory");
}

__global__ void k_scatter(const int* __restrict__ src,
                          const int* __restrict__ dst,
                          const float* __restrict__ hs,
                          float* __restrict__ acc,
                          long long E, int lf4) {           // lf4 = log2(F/4)
    long long idx = (long long)blockIdx.x * blockDim.x + threadIdx.x;
    long long total = E << lf4;
    if (idx >= total) return;
    long long e = idx >> lf4;
    int c = (int)(idx & ((1 << lf4) - 1));
    int s = src[e];
    int d = dst[e];
    const float4* hs4 = reinterpret_cast<const float4*>(hs);
    float4 v = hs4[((long long)s << lf4) + c];
    red_add_v4(reinterpret_cast<float4*>(acc) + (((long long)d << lf4) + c), v);
}

// ---------------- finalize: out = dinv*acc + b [, relu] ---------------------

__global__ void k_finalize(const float* __restrict__ acc,
                           const float* __restrict__ dinv,
                           const float* __restrict__ bias,
                           float* __restrict__ out,
                           long long total4, int lf4, int relu) {
    long long idx = (long long)blockIdx.x * blockDim.x + threadIdx.x;
    if (idx >= total4) return;
    long long n = idx >> lf4;
    int c = (int)(idx & ((1 << lf4) - 1));
    float4 v = reinterpret_cast<const float4*>(acc)[idx];
    float dv = dinv[n];
    float4 b = reinterpret_cast<const float4*>(bias)[c];
    v.x = v.x * dv + b.x;
    v.y = v.y * dv + b.y;
    v.z = v.z * dv + b.z;
    v.w = v.w * dv + b.w;
    if (relu) {
        v.x = fmaxf(v.x, 0.f); v.y = fmaxf(v.y, 0.f);
        v.z = fmaxf(v.z, 0.f); v.w = fmaxf(v.w, 0.f);
    }
    reinterpret_cast<float4*>(out)[idx] = v;
}

// ---------------- host side -------------------------------------------------

static inline int ilog2(int x) { int l = 0; while ((1 << l) < x) l++; return l; }

static void gcn_layer(const float* x, const int* edges, long long E,
                      const float* W, const float* bias, float* out,
                      int M, int K, int F, int shift, int relu,
                      float* deg, float* hs, float* acc) {
    const int* src = edges;
    const int* dst = edges + E;

    k_init_deg <<<(M + 255) / 256, 256>>>(deg, M);
    k_count_deg<<<((int)E + 255) / 256, 256>>>(dst, deg, (int)E);
    k_rsqrt    <<<(M + 255) / 256, 256>>>(deg, M);

    if (F >= 64) {
        dim3 grid(F / 64, (M + 63) / 64);
        k_gemm_tiled<<<grid, 256>>>(x, W, hs, acc, deg, M, K, F, shift);
    } else {
        int npb = 256 / F;
        k_gemm_small<<<(M + npb - 1) / npb, 256>>>(x, W, hs, acc, deg,
                                                   M, K, F, shift);
    }

    int lf4 = ilog2(F / 4);
    long long totE = E << lf4;
    k_scatter<<<(int)((totE + 255) / 256), 256>>>(src, dst, hs, acc, E, lf4);

    long long tot4 = (long long)M << lf4;
    k_finalize<<<(int)((tot4 + 255) / 256), 256>>>(acc, deg, bias, out,
                                                   tot4, lf4, relu);
}

extern "C" void kernel_launch(void* const* d_in, const int* in_sizes, int n_in,
                              void* d_out, int out_size) {
    const float* z   = (const float*)d_in[0];
    const int*   e1  = (const int*)d_in[1];
    const int*   ps2 = (const int*)d_in[2];
    const int*   ps1 = (const int*)d_in[3];
    const int*   ps0 = (const int*)d_in[4];
    const float* W1 = (const float*)d_in[5];
    const float* b1 = (const float*)d_in[6];
    const float* W2 = (const float*)d_in[7];
    const float* b2 = (const float*)d_in[8];
    const float* W3 = (const float*)d_in[9];
    const float* b3 = (const float*)d_in[10];
    const float* W4 = (const float*)d_in[11];
    const float* b4 = (const float*)d_in[12];

    const int h2 = 256, h1 = 128, h0 = 64, oc = 8;
    int N = in_sizes[0] / h2;                   // 25000
    long long E1 = in_sizes[1] / 2;
    long long E2 = in_sizes[2] / 2;
    long long E3 = in_sizes[3] / 2;
    long long E4 = in_sizes[4] / 2;

    float *deg, *hs, *acc, *p1, *p2;
    cudaGetSymbolAddress((void**)&deg, g_deg);
    cudaGetSymbolAddress((void**)&hs,  g_hs);
    cudaGetSymbolAddress((void**)&acc, g_acc);
    cudaGetSymbolAddress((void**)&p1,  g_p1);
    cudaGetSymbolAddress((void**)&p2,  g_p2);

    // L1: [N, 256] -> [N, 256], relu
    gcn_layer(z,  e1,  E1, W1, b1, p1, N,     h2, h2, 0, 1, deg, hs, acc);
    // L2 (upsample folded): [2N, 256] -> [2N, 128], relu
    gcn_layer(p1, ps2, E2, W2, b2, p2, 2 * N, h2, h1, 1, 1, deg, hs, acc);
    // L3: [4N, 128] -> [4N, 64], relu
    gcn_layer(p2, ps1, E3, W3, b3, p1, 4 * N, h1, h0, 1, 1, deg, hs, acc);
    // L4: [8N, 64] -> [8N, 8], no relu, straight to d_out
    gcn_layer(p1, ps0, E4, W4, b4, (float*)d_out, 8 * N, h0, oc, 1, 0,
              deg, hs, acc);
}